// round 1
// baseline (speedup 1.0000x reference)
#include <cuda_runtime.h>
#include <math_constants.h>

#define BATCH 2
#define CH    128
#define NSP   4096
#define GROUPS 8
#define TN    64
#define TM    128
#define EPSV  1e-5f

// ---------------- scratch (static __device__, allocation-free) ----------------
__device__ float g_Q [BATCH*CH*NSP];     // [b][c][n]
__device__ float g_K [BATCH*CH*NSP];     // [b][c][n]
__device__ float g_Vt[BATCH*NSP*CH];     // [b][m][c]  (pre-transposed V)
__device__ float g_H [BATCH*NSP*CH];     // [b][n][c]
__device__ float g_Y [BATCH*CH*NSP];     // [b][c][n]  (pre-norm residual sum)
__device__ float g_part [BATCH*64*GROUPS*2];
__device__ float g_stats[BATCH*GROUPS*2];

// ---------------- f32x2 helpers (Blackwell packed fp32) ----------------
__device__ __forceinline__ unsigned long long pk2(float x, float y){
    unsigned long long r; asm("mov.b64 %0, {%1,%2};" : "=l"(r) : "f"(x), "f"(y)); return r;
}
__device__ __forceinline__ void upk2(unsigned long long v, float& x, float& y){
    asm("mov.b64 {%0,%1}, %2;" : "=f"(x), "=f"(y) : "l"(v));
}
__device__ __forceinline__ void ffma2(unsigned long long& d, unsigned long long a, unsigned long long b){
    asm("fma.rn.f32x2 %0, %1, %2, %0;" : "+l"(d) : "l"(a), "l"(b));
}
__device__ __forceinline__ unsigned long long fmul2(unsigned long long a, unsigned long long b){
    unsigned long long d; asm("mul.rn.f32x2 %0, %1, %2;" : "=l"(d) : "l"(a), "l"(b)); return d;
}

// ============================================================================
// K1: Q/K/V projections.  out[o][n] = sum_c W[o][c] * x[b][c][n]
// grid (64 n-tiles, B, 3 mats). V is written transposed [m][c].
// smem: Wt [128][130] + Xs/stage region (8320 floats)
// ============================================================================
__global__ __launch_bounds__(256) void k_qkv(const float* __restrict__ x,
                                             const float* __restrict__ Wq,
                                             const float* __restrict__ Wk,
                                             const float* __restrict__ Wv)
{
    extern __shared__ float sm[];
    float* Wt = sm;               // [c][130]
    float* Xs = sm + 128*130;     // [c][64] during compute; [o][65] staging after

    const int n0  = blockIdx.x * TN;
    const int b   = blockIdx.y;
    const int z   = blockIdx.z;
    const float* W = (z == 0) ? Wq : ((z == 1) ? Wk : Wv);

    const int tid = threadIdx.x;
    const int tx  = tid & 15;
    const int ty  = tid >> 4;

    // W transposed into smem: Wt[c][o]
    for (int idx = tid; idx < 128*64; idx += 256){
        int o  = idx >> 6;
        int cq = (idx & 63) << 1;
        float2 w = *(const float2*)(W + o*128 + cq);
        Wt[ cq   *130 + o] = w.x;
        Wt[(cq+1)*130 + o] = w.y;
    }
    // X tile [c][64]
    const float* xb = x + (size_t)b*CH*NSP + n0;
    for (int idx = tid; idx < 128*16; idx += 256){
        int c = idx >> 4, u = (idx & 15) << 2;
        *(float4*)(Xs + c*64 + u) = *(const float4*)(xb + c*NSP + u);
    }
    __syncthreads();

    unsigned long long acc[4][4];
    #pragma unroll
    for (int i = 0; i < 4; i++)
        #pragma unroll
        for (int j = 0; j < 4; j++) acc[i][j] = 0ull;

    #pragma unroll 4
    for (int c = 0; c < 128; c++){
        unsigned long long wv[4]; float xn[4];
        #pragma unroll
        for (int j = 0; j < 4; j++)
            wv[j] = *(const unsigned long long*)(Wt + c*130 + 2*tx + 32*j);
        #pragma unroll
        for (int i = 0; i < 4; i++) xn[i] = Xs[c*64 + ty + 16*i];
        #pragma unroll
        for (int i = 0; i < 4; i++){
            unsigned long long xd = pk2(xn[i], xn[i]);
            #pragma unroll
            for (int j = 0; j < 4; j++) ffma2(acc[i][j], wv[j], xd);
        }
    }
    __syncthreads();

    // stage [o][65]
    float* St = Xs;
    #pragma unroll
    for (int i = 0; i < 4; i++)
        #pragma unroll
        for (int j = 0; j < 4; j++){
            float a, bv; upk2(acc[i][j], a, bv);
            int o = 2*tx + 32*j, n = ty + 16*i;
            St[ o   *65 + n] = a;
            St[(o+1)*65 + n] = bv;
        }
    __syncthreads();

    if (z < 2){
        float* out = (z == 0 ? g_Q : g_K) + (size_t)b*CH*NSP + n0;
        for (int k = 0; k < 32; k++){
            int e = k*256 + tid; int o = e >> 6, n = e & 63;
            out[o*NSP + n] = St[o*65 + n];
        }
    } else {
        float* out = g_Vt + (size_t)b*NSP*CH + (size_t)n0*CH;
        for (int k = 0; k < 32; k++){
            int e = k*256 + tid; int n = e >> 7, o = e & 127;
            out[n*CH + o] = St[o*65 + n];
        }
    }
}

// ============================================================================
// K2: flash attention.  CTA = (64 queries, b). Online softmax over 32 key
// tiles of 128.  S[n][m] = sum_c Q[c][n]K[c][m];  O[n][c] += P[n][m]Vt[m][c].
// smem: QS[128][64] KS[128][128] VT[128][132] PS[64][130]
// ============================================================================
__global__ __launch_bounds__(256) void k_attn()
{
    extern __shared__ float sm[];
    float* QS = sm;                 // 8192
    float* KS = QS + 128*64;        // 16384
    float* VT = KS + 128*128;       // 16896
    float* PS = VT + 128*132;       // 8320 (also staging for H)

    const int n0 = blockIdx.x * TN;
    const int b  = blockIdx.y;
    const int tid = threadIdx.x;
    const int tx  = tid & 15;
    const int ty  = tid >> 4;

    const float* Qb = g_Q  + (size_t)b*CH*NSP + n0;
    const float* Kb = g_K  + (size_t)b*CH*NSP;
    const float* Vb = g_Vt + (size_t)b*NSP*CH;

    for (int idx = tid; idx < 128*16; idx += 256){
        int c = idx >> 4, u = (idx & 15) << 2;
        *(float4*)(QS + c*64 + u) = *(const float4*)(Qb + c*NSP + u);
    }

    unsigned long long oacc[4][4];
    #pragma unroll
    for (int i = 0; i < 4; i++)
        #pragma unroll
        for (int j = 0; j < 4; j++) oacc[i][j] = 0ull;
    float mrow[4] = {-CUDART_INF_F, -CUDART_INF_F, -CUDART_INF_F, -CUDART_INF_F};
    float lrow[4] = {0.f, 0.f, 0.f, 0.f};

    for (int m0 = 0; m0 < NSP; m0 += TM){
        __syncthreads();   // covers QS fill (1st iter) and prior O-accum reads of KS/VT
        for (int idx = tid; idx < 128*32; idx += 256){
            int c = idx >> 5, u = (idx & 31) << 2;
            *(float4*)(KS + c*128 + u) = *(const float4*)(Kb + c*NSP + m0 + u);
        }
        for (int idx = tid; idx < 128*32; idx += 256){
            int m = idx >> 5, u = (idx & 31) << 2;
            *(float4*)(VT + m*132 + u) = *(const float4*)(Vb + (size_t)(m0+m)*CH + u);
        }
        __syncthreads();

        // ---- S = Q^T K (f32x2 over m-pairs) ----
        unsigned long long s[4][4];
        #pragma unroll
        for (int i = 0; i < 4; i++)
            #pragma unroll
            for (int j = 0; j < 4; j++) s[i][j] = 0ull;

        #pragma unroll 2
        for (int c = 0; c < 128; c++){
            unsigned long long kv[4]; float qv[4];
            #pragma unroll
            for (int j = 0; j < 4; j++)
                kv[j] = *(const unsigned long long*)(KS + c*128 + 2*tx + 32*j);
            #pragma unroll
            for (int i = 0; i < 4; i++) qv[i] = QS[c*64 + ty + 16*i];
            #pragma unroll
            for (int i = 0; i < 4; i++){
                unsigned long long qd = pk2(qv[i], qv[i]);
                #pragma unroll
                for (int j = 0; j < 4; j++) ffma2(s[i][j], kv[j], qd);
            }
        }

        // ---- online softmax per row ----
        #pragma unroll
        for (int i = 0; i < 4; i++){
            float p[8];
            #pragma unroll
            for (int j = 0; j < 4; j++) upk2(s[i][j], p[2*j], p[2*j+1]);
            float mx = p[0];
            #pragma unroll
            for (int j = 1; j < 8; j++) mx = fmaxf(mx, p[j]);
            #pragma unroll
            for (int d = 1; d < 16; d <<= 1) mx = fmaxf(mx, __shfl_xor_sync(0xffffffffu, mx, d));
            float mnew = fmaxf(mrow[i], mx);
            float al   = __expf(mrow[i] - mnew);
            mrow[i]    = mnew;
            float sum = 0.f;
            #pragma unroll
            for (int j = 0; j < 8; j++){ p[j] = __expf(p[j] - mnew); sum += p[j]; }
            int nrow = ty + 16*i;
            #pragma unroll
            for (int j = 0; j < 4; j++)
                *(float2*)(PS + nrow*130 + 2*tx + 32*j) = make_float2(p[2*j], p[2*j+1]);
            #pragma unroll
            for (int d = 1; d < 16; d <<= 1) sum += __shfl_xor_sync(0xffffffffu, sum, d);
            lrow[i] = lrow[i]*al + sum;
            unsigned long long ad = pk2(al, al);
            #pragma unroll
            for (int j = 0; j < 4; j++) oacc[i][j] = fmul2(oacc[i][j], ad);
        }
        __syncthreads();

        // ---- O += P Vt (f32x2 over c-pairs) ----
        #pragma unroll 2
        for (int m = 0; m < 128; m++){
            unsigned long long vv[4]; float pv[4];
            #pragma unroll
            for (int j = 0; j < 4; j++)
                vv[j] = *(const unsigned long long*)(VT + m*132 + 2*tx + 32*j);
            #pragma unroll
            for (int i = 0; i < 4; i++) pv[i] = PS[(ty + 16*i)*130 + m];
            #pragma unroll
            for (int i = 0; i < 4; i++){
                unsigned long long pd = pk2(pv[i], pv[i]);
                #pragma unroll
                for (int j = 0; j < 4; j++) ffma2(oacc[i][j], vv[j], pd);
            }
        }
    }
    __syncthreads();

    // normalize + stage [n][c] into PS, then coalesced write to g_H
    #pragma unroll
    for (int i = 0; i < 4; i++){
        float inv = 1.0f / lrow[i];
        unsigned long long id = pk2(inv, inv);
        int nrow = ty + 16*i;
        #pragma unroll
        for (int j = 0; j < 4; j++){
            unsigned long long o2 = fmul2(oacc[i][j], id);
            float a, bv; upk2(o2, a, bv);
            *(float2*)(PS + nrow*130 + 2*tx + 32*j) = make_float2(a, bv);
        }
    }
    __syncthreads();
    float* Hb = g_H + (size_t)b*NSP*CH + (size_t)n0*CH;
    for (int k = 0; k < 32; k++){
        int e = k*256 + tid; int n = e >> 7, c = e & 127;
        Hb[n*CH + c] = PS[n*130 + c];
    }
}

// ============================================================================
// K3: y = x + Wo @ h, plus deterministic per-(b,group) partial sums.
// smem: Wot[128][130] + HS region (8320 floats; [n][129] then [o][65] staging)
// ============================================================================
__global__ __launch_bounds__(256) void k_proj(const float* __restrict__ x,
                                              const float* __restrict__ Wo)
{
    extern __shared__ float sm[];
    float* Wt = sm;               // [c][130]
    float* HS = sm + 128*130;     // [n][129] compute; [o][65] staging

    const int n0 = blockIdx.x * TN;
    const int b  = blockIdx.y;
    const int tid = threadIdx.x;
    const int tx  = tid & 15;
    const int ty  = tid >> 4;

    for (int idx = tid; idx < 128*64; idx += 256){
        int o  = idx >> 6;
        int cq = (idx & 63) << 1;
        float2 w = *(const float2*)(Wo + o*128 + cq);
        Wt[ cq   *130 + o] = w.x;
        Wt[(cq+1)*130 + o] = w.y;
    }
    const float* Hb = g_H + (size_t)b*NSP*CH + (size_t)n0*CH;
    for (int idx = tid; idx < 64*128; idx += 256){
        int n = idx >> 7, c = idx & 127;
        HS[n*129 + c] = Hb[idx];
    }
    __syncthreads();

    unsigned long long acc[4][4];
    #pragma unroll
    for (int i = 0; i < 4; i++)
        #pragma unroll
        for (int j = 0; j < 4; j++) acc[i][j] = 0ull;

    #pragma unroll 4
    for (int c = 0; c < 128; c++){
        unsigned long long wv[4]; float hv[4];
        #pragma unroll
        for (int j = 0; j < 4; j++)
            wv[j] = *(const unsigned long long*)(Wt + c*130 + 2*tx + 32*j);
        #pragma unroll
        for (int i = 0; i < 4; i++) hv[i] = HS[(ty + 16*i)*129 + c];
        #pragma unroll
        for (int i = 0; i < 4; i++){
            unsigned long long hd = pk2(hv[i], hv[i]);
            #pragma unroll
            for (int j = 0; j < 4; j++) ffma2(acc[i][j], wv[j], hd);
        }
    }
    __syncthreads();

    float* St = HS;  // [o][65]
    #pragma unroll
    for (int i = 0; i < 4; i++)
        #pragma unroll
        for (int j = 0; j < 4; j++){
            float a, bv; upk2(acc[i][j], a, bv);
            int o = 2*tx + 32*j, n = ty + 16*i;
            St[ o   *65 + n] = a;
            St[(o+1)*65 + n] = bv;
        }
    __syncthreads();

    const float* xb = x   + (size_t)b*CH*NSP + n0;
    float*       yb = g_Y + (size_t)b*CH*NSP + n0;
    const int w = tid >> 5, lane = tid & 31;
    float s1 = 0.f, s2 = 0.f;
    for (int k = 0; k < 32; k++){
        int e = w*1024 + k*32 + lane;       // warp w covers channels [16w,16w+16) = group w
        int o = e >> 6, n = e & 63;
        float val = xb[o*NSP + n] + St[o*65 + n];
        yb[o*NSP + n] = val;
        s1 += val; s2 += val*val;
    }
    #pragma unroll
    for (int d = 16; d >= 1; d >>= 1){
        s1 += __shfl_xor_sync(0xffffffffu, s1, d);
        s2 += __shfl_xor_sync(0xffffffffu, s2, d);
    }
    if (lane == 0){
        float* p = g_part + ((size_t)(b*64 + blockIdx.x)*GROUPS + w)*2;
        p[0] = s1; p[1] = s2;
    }
}

// K3b: deterministic reduction of partials. 1 block, 512 threads (warp per (b,g)).
__global__ void k_red()
{
    int w = threadIdx.x >> 5, lane = threadIdx.x & 31;
    int b = w >> 3, g = w & 7;
    float s1 = 0.f, s2 = 0.f;
    for (int t = lane; t < 64; t += 32){
        const float* p = g_part + ((size_t)(b*64 + t)*GROUPS + g)*2;
        s1 += p[0]; s2 += p[1];
    }
    #pragma unroll
    for (int d = 16; d >= 1; d >>= 1){
        s1 += __shfl_xor_sync(0xffffffffu, s1, d);
        s2 += __shfl_xor_sync(0xffffffffu, s2, d);
    }
    if (lane == 0){
        g_stats[(b*GROUPS + g)*2 + 0] = s1;
        g_stats[(b*GROUPS + g)*2 + 1] = s2;
    }
}

// K4: GroupNorm + affine + SiLU, elementwise (float4).
__global__ __launch_bounds__(256) void k_norm(const float* __restrict__ gamma,
                                              const float* __restrict__ beta,
                                              float* __restrict__ out)
{
    int gid = blockIdx.x * blockDim.x + threadIdx.x;
    int e = gid << 2;
    int b = e >> 19;               // CH*NSP = 2^19
    int c = (e >> 12) & 127;       // NSP = 2^12
    int g = c >> 4;
    float s  = g_stats[(b*GROUPS + g)*2 + 0];
    float ss = g_stats[(b*GROUPS + g)*2 + 1];
    const float icnt = 1.0f / 65536.0f;   // (CH/GROUPS)*NSP
    float mean = s * icnt;
    float var  = ss * icnt - mean*mean;
    float inv  = rsqrtf(var + EPSV);
    float ga = gamma[c], be = beta[c];

    float4 y = *(const float4*)(g_Y + e);
    float4 r;
    {
        float t = (y.x - mean)*inv*ga + be; r.x = t / (1.0f + __expf(-t));
        t = (y.y - mean)*inv*ga + be;       r.y = t / (1.0f + __expf(-t));
        t = (y.z - mean)*inv*ga + be;       r.z = t / (1.0f + __expf(-t));
        t = (y.w - mean)*inv*ga + be;       r.w = t / (1.0f + __expf(-t));
    }
    *(float4*)(out + e) = r;
}

// ============================================================================
extern "C" void kernel_launch(void* const* d_in, const int* in_sizes, int n_in,
                              void* d_out, int out_size)
{
    const float* x     = (const float*)d_in[0];
    const float* Wq    = (const float*)d_in[1];
    const float* Wk    = (const float*)d_in[2];
    const float* Wv    = (const float*)d_in[3];
    const float* Wo    = (const float*)d_in[4];
    const float* gamma = (const float*)d_in[5];
    const float* beta  = (const float*)d_in[6];
    float* out = (float*)d_out;

    const int SM1 = (128*130 + 128*65) * 4;                       // 99840 B
    const int SM2 = (128*64 + 128*128 + 128*132 + 64*130) * 4;    // 199168 B
    const int SM3 = (128*130 + 128*65) * 4;                       // 99840 B

    cudaFuncSetAttribute(k_qkv,  cudaFuncAttributeMaxDynamicSharedMemorySize, SM1);
    cudaFuncSetAttribute(k_attn, cudaFuncAttributeMaxDynamicSharedMemorySize, SM2);
    cudaFuncSetAttribute(k_proj, cudaFuncAttributeMaxDynamicSharedMemorySize, SM3);

    k_qkv <<<dim3(NSP/TN, BATCH, 3), 256, SM1>>>(x, Wq, Wk, Wv);
    k_attn<<<dim3(NSP/TN, BATCH),    256, SM2>>>();
    k_proj<<<dim3(NSP/TN, BATCH),    256, SM3>>>(x, Wo);
    k_red <<<1, 512>>>();
    k_norm<<<(BATCH*CH*NSP)/(4*256), 256>>>(gamma, beta, out);
}